// round 12
// baseline (speedup 1.0000x reference)
#include <cuda_runtime.h>
#include <cuda_bf16.h>
#include <cstdint>

#define BB 4
#define HH 48
#define WW 48
#define CC 128

typedef unsigned int u32;
typedef unsigned long long u64;

// ---------------- scratch (device globals; no allocation allowed) ----------
__device__ float g_F [BB*HH*WW*CC];                 // raw features, pixel-major
__device__ float g_FN[BB*HH*WW*CC];                 // layernormed features
__device__ __nv_bfloat16 g_Qb   [BB*HH*WW*CC];      // queries, bf16, pre-scaled
__device__ __nv_bfloat16 g_KVh  [BB*HH*WW*256];     // per-pixel KV, bf16
__device__ __nv_bfloat16 g_KVmidh[BB*24*24*256];    // 2x2 pooled KV, bf16
__device__ __nv_bfloat16 g_KVgloh[BB*12*12*256];    // 4x4 pooled KV, bf16
__device__ __nv_bfloat16 g_kvbh [256];              // bias token, bf16

__device__ __forceinline__ float ex2f(float x) {
    float r; asm("ex2.approx.f32 %0, %1;" : "=f"(r) : "f"(x)); return r;
}
__device__ __forceinline__ u32 packbf(float lo, float hi) {
    u32 r; asm("cvt.rn.satfinite.bf16x2.f32 %0, %1, %2;" : "=r"(r) : "f"(hi), "f"(lo));
    return r;
}
__device__ __forceinline__ u64 ffma2(u64 a, u64 b, u64 c) {
    u64 d; asm("fma.rn.f32x2 %0,%1,%2,%3;" : "=l"(d) : "l"(a), "l"(b), "l"(c)); return d;
}
__device__ __forceinline__ void up2(u64 v, float& lo, float& hi) {
    asm("mov.b64 {%0,%1},%2;" : "=f"(lo), "=f"(hi) : "l"(v));
}
// D += A(bf16) * B(bf16), fp32 accum, m16n8k16 row.col
__device__ __forceinline__ void mma_bf16(float d[4], const u32 a[4], const u32 b[2]) {
    asm volatile(
        "mma.sync.aligned.m16n8k16.row.col.f32.bf16.bf16.f32 "
        "{%0,%1,%2,%3},{%4,%5,%6,%7},{%8,%9},{%0,%1,%2,%3};"
        : "+f"(d[0]), "+f"(d[1]), "+f"(d[2]), "+f"(d[3])
        : "r"(a[0]), "r"(a[1]), "r"(a[2]), "r"(a[3]), "r"(b[0]), "r"(b[1]));
}

// ============================================================================
// Kernel 0: transpose NCHW -> pixel-major + LayerNorm.  Unchanged.
// ============================================================================
__global__ void k0_ln(const float* __restrict__ feat,
                      const float* __restrict__ lnw,
                      const float* __restrict__ lnb) {
    int warp = (blockIdx.x * blockDim.x + threadIdx.x) >> 5;
    int lane = threadIdx.x & 31;
    if (warp >= BB*HH*WW) return;
    int b   = warp / (HH*WW);
    int rem = warp % (HH*WW);
    const float* src = feat + (size_t)b * CC * HH * WW + rem;

    float v[4];
    float s = 0.f, ss = 0.f;
#pragma unroll
    for (int i = 0; i < 4; i++) {
        int c = lane + 32*i;
        v[i] = src[(size_t)c * (HH*WW)];
        s  += v[i];
        ss += v[i]*v[i];
    }
#pragma unroll
    for (int o = 16; o; o >>= 1) {
        s  += __shfl_xor_sync(0xffffffffu, s,  o);
        ss += __shfl_xor_sync(0xffffffffu, ss, o);
    }
    float mean = s * (1.f/128.f);
    float var  = ss * (1.f/128.f) - mean*mean;
    float rstd = rsqrtf(var + 1e-5f);

    float* dF = g_F  + (size_t)warp * CC;
    float* dN = g_FN + (size_t)warp * CC;
#pragma unroll
    for (int i = 0; i < 4; i++) {
        int c = lane + 32*i;
        dF[c] = v[i];
        dN[c] = (v[i] - mean) * rstd * lnw[c] + lnb[c];
    }
}

// ============================================================================
// Kernel 1: fused GEMMs (bf16 epilogue; Q pre-scaled).  Unchanged from R11.
// ============================================================================
#define MT 64
#define PADK 36

__global__ void k1_gemm(const float* __restrict__ qw, const float* __restrict__ qb,
                        const float* __restrict__ kvw, const float* __restrict__ kvb) {
    __shared__ float sA[MT][PADK];
    __shared__ float sB[128][PADK];

    int sub   = blockIdx.y;
    int mBase = blockIdx.x * MT;
    const float* A    = (sub == 0) ? g_FN : g_F;
    const float* Wm   = (sub == 0) ? qw : (kvw + (size_t)(sub-1)*128*128);
    const float* bias = (sub == 0) ? qb : (kvb + (sub-1)*128);

    int tid = threadIdx.x;
    int mg = tid & 15;
    int ng = tid >> 4;

    float acc[4][8];
#pragma unroll
    for (int m = 0; m < 4; m++)
#pragma unroll
        for (int n = 0; n < 8; n++) acc[m][n] = 0.f;

    for (int ck = 0; ck < 4; ck++) {
        __syncthreads();
#pragma unroll
        for (int i = 0; i < 2; i++) {
            int f = tid + i*256;
            int pix = f >> 3, kq = f & 7;
            float4 val = *(const float4*)(A + (size_t)(mBase+pix)*128 + ck*32 + kq*4);
            *(float4*)&sA[pix][kq*4] = val;
        }
#pragma unroll
        for (int i = 0; i < 4; i++) {
            int f = tid + i*256;
            int row = f >> 3, kq = f & 7;
            float4 val = *(const float4*)(Wm + (size_t)row*128 + ck*32 + kq*4);
            *(float4*)&sB[row][kq*4] = val;
        }
        __syncthreads();

#pragma unroll
        for (int k4 = 0; k4 < 8; k4++) {
            float4 a0 = *(const float4*)&sA[mg*4+0][k4*4];
            float4 a1 = *(const float4*)&sA[mg*4+1][k4*4];
            float4 a2 = *(const float4*)&sA[mg*4+2][k4*4];
            float4 a3 = *(const float4*)&sA[mg*4+3][k4*4];
#pragma unroll
            for (int n = 0; n < 8; n++) {
                float4 bv = *(const float4*)&sB[ng*8+n][k4*4];
                acc[0][n] += a0.x*bv.x + a0.y*bv.y + a0.z*bv.z + a0.w*bv.w;
                acc[1][n] += a1.x*bv.x + a1.y*bv.y + a1.z*bv.z + a1.w*bv.w;
                acc[2][n] += a2.x*bv.x + a2.y*bv.y + a2.z*bv.z + a2.w*bv.w;
                acc[3][n] += a3.x*bv.x + a3.y*bv.y + a3.z*bv.z + a3.w*bv.w;
            }
        }
    }

    const float SC = 0.25f * 1.4426950408889634f;
    float bv[8];
#pragma unroll
    for (int n = 0; n < 8; n++) bv[n] = bias[ng*8 + n];

#pragma unroll
    for (int m = 0; m < 4; m++) {
        int row = mBase + mg*4 + m;
        float v[8];
#pragma unroll
        for (int n = 0; n < 8; n++) {
            v[n] = acc[m][n] + bv[n];
            if (sub == 0) v[n] *= SC;
        }
        uint4 pk;
        pk.x = packbf(v[0], v[1]);
        pk.y = packbf(v[2], v[3]);
        pk.z = packbf(v[4], v[5]);
        pk.w = packbf(v[6], v[7]);
        __nv_bfloat16* dst = (sub == 0)
            ? (g_Qb  + (size_t)row*128 + ng*8)
            : (g_KVh + (size_t)row*256 + (sub-1)*128 + ng*8);
        *(uint4*)dst = pk;
    }
}

// ============================================================================
// Kernel 2: pooled KV (bf16) + bias token.  Unchanged from R11.
// ============================================================================
__global__ void k2_pool(const float* __restrict__ kvb) {
    int t = blockIdx.x;
    int c = threadIdx.x;
    if (t < BB*576) {
        int b = t / 576, r = t % 576, my = r / 24, mx = r % 24;
        const __nv_bfloat16* base = g_KVh + ((size_t)((b*48 + my*2)*48 + mx*2))*256 + c;
        float v = __bfloat162float(base[0]) + __bfloat162float(base[256])
                + __bfloat162float(base[48*256]) + __bfloat162float(base[48*256 + 256]);
        g_KVmidh[(size_t)t*256 + c] = __float2bfloat16(v * 0.25f);
    } else if (t < BB*576 + BB*144) {
        int t2 = t - BB*576;
        int b = t2 / 144, r = t2 % 144, gy = r / 12, gx = r % 12;
        float v = 0.f;
#pragma unroll
        for (int i = 0; i < 4; i++)
#pragma unroll
            for (int j = 0; j < 4; j++)
                v += __bfloat162float(
                    g_KVh[((size_t)((b*48 + gy*4 + i)*48 + gx*4 + j))*256 + c]);
        g_KVgloh[(size_t)t2*256 + c] = __float2bfloat16(v * (1.f/16.f));
    } else {
        g_kvbh[c] = __float2bfloat16(kvb[c]);
    }
}

// ============================================================================
// Kernel 3 v11: HMMA flash attention, fragments loaded DIRECTLY FROM GMEM
//   (L2-resident).  No staging, no mainloop barriers — warps independent.
//   16 warps = 8 heads x 2 q-halves; warp iterates its own 53-tile list
//   (8 own-window local tiles + 45 mid/glo), software-pipelined with two
//   named frag buffers (loads for t+2 issued after compute(t)).
//   Epilogue identical to R11 (validated).
// ============================================================================
#define SMEMB (64*132*4*2)          // att + wsm = 67584 B

struct Frag {
    u32 k[4];      // K b-frags raw (2 n-tiles x 2)
    u32 v[8];      // V u16 raw halves (2 vd x 4)
};

__global__ void __launch_bounds__(512, 1)
k3_attn(const float* __restrict__ feat, const float* __restrict__ ow,
        const float* __restrict__ ob,   float* __restrict__ out) {
    extern __shared__ float ds[];

    int cta = blockIdx.x;
    int b = cta / 36, g = cta % 36;
    int gy = g / 6, gx = g % 6;
    int tid  = threadIdx.x;
    int lane = tid & 31;
    int warp = tid >> 5;
    int h = warp & 7, mh = warp >> 3;      // head, query-half (2 m-tiles)
    int t4 = lane & 3, g4 = lane >> 2;

    // ---- Q A-frags (once; already scaled) ----
    u32 aQ[2][4];
    {
        const u32* qp = (const u32*)g_Qb;
#pragma unroll
        for (int m = 0; m < 2; m++) {
            int wg = mh*2 + m;
            int wy = gy*2 + (wg>>1), wx = gx*2 + (wg&1);
            int qa = g4,     pya = wy*4 + (qa>>2), pxa = wx*4 + (qa&3);
            int qb2 = g4+8,  pyb = wy*4 + (qb2>>2), pxb = wx*4 + (qb2&3);
            size_t pa = (size_t)((b*48+pya)*48+pxa)*64 + h*8 + t4;
            size_t pb = (size_t)((b*48+pyb)*48+pxb)*64 + h*8 + t4;
            aQ[m][0] = qp[pa];     aQ[m][1] = qp[pb];
            aQ[m][2] = qp[pa+4];   aQ[m][3] = qp[pb+4];
        }
    }

    float o[2][2][4];
#pragma unroll
    for (int m = 0; m < 2; m++)
#pragma unroll
        for (int n = 0; n < 2; n++)
#pragma unroll
            for (int i = 0; i < 4; i++) o[m][n][i] = 0.f;
    float ls[2][2] = {{0.f,0.f},{0.f,0.f}};

    // warp's tile list: ti<8 -> own local tiles (8*mh..8*mh+7), else mid/glo
    auto ttof = [&](int ti) { return (ti < 8) ? (8*mh + ti) : (ti + 8); };

    // row pointer for token-row r of tile tt
    auto rowptr = [&](int tt, int r) -> const __nv_bfloat16* {
        if (tt < 16) {
            int wgl = tt >> 2, st = tt & 3;
            int id2 = st*16 + r;
            int y = (gy*2 + (wgl>>1))*4 + (id2>>3) - 2;
            int x = (gx*2 + (wgl&1))*4  + (id2&7)  - 2;
            return ((unsigned)y < 48u && (unsigned)x < 48u)
                ? (g_KVh + ((size_t)((b*48+y)*48+x))*256) : g_kvbh;
        } else if (tt < 52) {
            return g_KVmidh + ((size_t)(b*576 + (tt-16)*16 + r))*256;
        } else {
            return g_KVgloh + ((size_t)(b*144 + (tt-52)*16 + r))*256;
        }
    };

    // fragment load for tile tt (12 LDGs, no combines)
    auto loadf = [&](int tt, Frag& F) {
        const __nv_bfloat16* rk0 = rowptr(tt, g4);
        const __nv_bfloat16* rk1 = rowptr(tt, g4 + 8);
        int kc = h*8 + t4;                   // u32 column
        F.k[0] = ((const u32*)rk0)[kc];
        F.k[1] = ((const u32*)rk0)[kc+4];
        F.k[2] = ((const u32*)rk1)[kc];
        F.k[3] = ((const u32*)rk1)[kc+4];

        const __nv_bfloat16* rv0 = rowptr(tt, 2*t4);
        const __nv_bfloat16* rv1 = rowptr(tt, 2*t4 + 1);
        const __nv_bfloat16* rv2 = rowptr(tt, 2*t4 + 8);
        const __nv_bfloat16* rv3 = rowptr(tt, 2*t4 + 9);
#pragma unroll
        for (int vd = 0; vd < 2; vd++) {
            int col = 128 + h*16 + vd*8 + g4;
            F.v[vd*4+0] = (u32)*(const unsigned short*)(rv0 + col);
            F.v[vd*4+1] = (u32)*(const unsigned short*)(rv1 + col);
            F.v[vd*4+2] = (u32)*(const unsigned short*)(rv2 + col);
            F.v[vd*4+3] = (u32)*(const unsigned short*)(rv3 + col);
        }
    };

    // tensor-core compute for tile tt using frag F
    auto compute = [&](const Frag& F, int tt) {
        u32 bK[2][2];
        bK[0][0] = F.k[0]; bK[0][1] = F.k[1];
        bK[1][0] = F.k[2]; bK[1][1] = F.k[3];
        u32 bV[2][2];
#pragma unroll
        for (int vd = 0; vd < 2; vd++) {
            bV[vd][0] = F.v[vd*4+0] | (F.v[vd*4+1] << 16);
            bV[vd][1] = F.v[vd*4+2] | (F.v[vd*4+3] << 16);
        }
        int m0 = 0, m1 = 2;
        if (tt < 16) { m0 = (tt >> 2) & 1; m1 = m0 + 1; }
        for (int m = m0; m < m1; m++) {
            float S[2][4];
#pragma unroll
            for (int n = 0; n < 2; n++) {
#pragma unroll
                for (int i = 0; i < 4; i++) S[n][i] = 0.f;
                mma_bf16(S[n], aQ[m], bK[n]);
#pragma unroll
                for (int i = 0; i < 4; i++) S[n][i] = ex2f(S[n][i]);
                ls[m][0] += S[n][0] + S[n][1];
                ls[m][1] += S[n][2] + S[n][3];
            }
            u32 aP[4];
            aP[0] = packbf(S[0][0], S[0][1]);
            aP[1] = packbf(S[0][2], S[0][3]);
            aP[2] = packbf(S[1][0], S[1][1]);
            aP[3] = packbf(S[1][2], S[1][3]);
#pragma unroll
            for (int vd = 0; vd < 2; vd++)
                mma_bf16(o[m][vd], aP, bV[vd]);
        }
    };

    // ---- software-pipelined mainloop over this warp's 53 tiles ----
    Frag FA, FB;
    loadf(ttof(0), FA);
    loadf(ttof(1), FB);
    for (int ti = 0; ti < 53; ti += 2) {
        compute(FA, ttof(ti));
        if (ti + 2 < 53) loadf(ttof(ti+2), FA);
        if (ti + 1 < 53) compute(FB, ttof(ti+1));
        if (ti + 3 < 53) loadf(ttof(ti+3), FB);
    }

    // ---- reduce ls across the 4 lanes of each row group ----
#pragma unroll
    for (int m = 0; m < 2; m++)
#pragma unroll
        for (int r = 0; r < 2; r++) {
            float v = ls[m][r];
            v += __shfl_xor_sync(0xffffffffu, v, 1);
            v += __shfl_xor_sync(0xffffffffu, v, 2);
            ls[m][r] = v;
        }

    // ---- normalize O frags -> att smem ----
    float* att = ds;                    // [64][132]
    float* wsm = ds + 64*132;           // [64][132]
#pragma unroll
    for (int m = 0; m < 2; m++) {
        float inv0 = 1.f / ls[m][0];
        float inv1 = 1.f / ls[m][1];
        int r0 = mh*32 + m*16 + g4;
#pragma unroll
        for (int n = 0; n < 2; n++) {
            int col = h*16 + n*8 + 2*t4;
            *(float2*)&att[r0*132 + col]     = make_float2(o[m][n][0]*inv0, o[m][n][1]*inv0);
            *(float2*)&att[(r0+8)*132 + col] = make_float2(o[m][n][2]*inv1, o[m][n][3]*inv1);
        }
    }
    __syncthreads();

    // ---- out projection: 2 chunks of 64 weight rows (validated) ----
    int aqi = tid >> 3, og = tid & 7;
    float ov[16];
#pragma unroll 1
    for (int c2 = 0; c2 < 2; c2++) {
#pragma unroll
        for (int i = 0; i < 4; i++) {
            int f = tid + i*512;
            int row = f >> 5, quad = f & 31;
            *(float4*)&wsm[row*132 + quad*4] =
                *(const float4*)(ow + (size_t)(c2*64 + row)*128 + quad*4);
        }
        __syncthreads();

        u64 r[8];
#pragma unroll
        for (int u2 = 0; u2 < 8; u2++) r[u2] = 0ull;
#pragma unroll 4
        for (int k4 = 0; k4 < 32; k4++) {
            longlong2 av = *(const longlong2*)&att[aqi*132 + k4*4];
#pragma unroll
            for (int u2 = 0; u2 < 8; u2++) {
                longlong2 wv = *(const longlong2*)&wsm[(u2*8+og)*132 + k4*4];
                r[u2] = ffma2((u64)av.x, (u64)wv.x, r[u2]);
                r[u2] = ffma2((u64)av.y, (u64)wv.y, r[u2]);
            }
        }
#pragma unroll
        for (int u2 = 0; u2 < 8; u2++) {
            float a, bb;
            up2(r[u2], a, bb);
            ov[c2*8 + u2] = a + bb;
        }
        __syncthreads();
    }

    // ---- residual add + NCHW scatter store ----
    {
        int qi = aqi & 15, wq = aqi >> 4;
        int wy = gy*2 + (wq>>1), wx = gx*2 + (wq&1);
        int py = wy*4 + (qi>>2), px = wx*4 + (qi&3);
#pragma unroll
        for (int c2 = 0; c2 < 2; c2++) {
#pragma unroll
            for (int u2 = 0; u2 < 8; u2++) {
                int oc = c2*64 + u2*8 + og;
                size_t gi = (((size_t)b*128 + oc)*48 + py)*48 + px;
                out[gi] = ov[c2*8+u2] + ob[oc] + feat[gi];
            }
        }
    }
}

// ============================================================================
extern "C" void kernel_launch(void* const* d_in, const int* in_sizes, int n_in,
                              void* d_out, int out_size) {
    const float* feat = (const float*)d_in[0];
    const float* lnw  = (const float*)d_in[1];
    const float* lnb  = (const float*)d_in[2];
    const float* qw   = (const float*)d_in[3];
    const float* qb   = (const float*)d_in[4];
    const float* kvw  = (const float*)d_in[5];
    const float* kvb  = (const float*)d_in[6];
    const float* ow   = (const float*)d_in[7];
    const float* ob   = (const float*)d_in[8];
    float* out = (float*)d_out;

    cudaFuncSetAttribute(k3_attn, cudaFuncAttributeMaxDynamicSharedMemorySize, SMEMB);

    k0_ln<<<1152, 256>>>(feat, lnw, lnb);
    k1_gemm<<<dim3(144, 3), 256>>>(qw, qb, kvw, kvb);
    k2_pool<<<2881, 256>>>(kvb);
    k3_attn<<<144, 512, SMEMB>>>(feat, ow, ob, out);
}

// round 13
// speedup vs baseline: 1.3376x; 1.3376x over previous
#include <cuda_runtime.h>
#include <cuda_bf16.h>
#include <cstdint>

#define BB 4
#define HH 48
#define WW 48
#define CC 128

typedef unsigned int u32;
typedef unsigned long long u64;

// ---------------- scratch (device globals; no allocation allowed) ----------
__device__ __nv_bfloat16 g_Fb [BB*HH*WW*CC];        // raw features, bf16 pixel-major
__device__ __nv_bfloat16 g_FNb[BB*HH*WW*CC];        // LN'd features, bf16
__device__ __nv_bfloat16 g_Wb [384*128];            // qw|kvw weights, bf16
__device__ __nv_bfloat16 g_Qb   [BB*HH*WW*CC];      // queries, bf16, pre-scaled
__device__ __nv_bfloat16 g_KVh  [BB*HH*WW*256];     // per-pixel KV, bf16
__device__ __nv_bfloat16 g_KVmidh[BB*24*24*256];    // 2x2 pooled KV, bf16
__device__ __nv_bfloat16 g_KVgloh[BB*12*12*256];    // 4x4 pooled KV, bf16
__device__ __nv_bfloat16 g_kvbh [256];              // bias token, bf16

__device__ __forceinline__ float ex2f(float x) {
    float r; asm("ex2.approx.f32 %0, %1;" : "=f"(r) : "f"(x)); return r;
}
__device__ __forceinline__ u32 packbf(float lo, float hi) {
    u32 r; asm("cvt.rn.satfinite.bf16x2.f32 %0, %1, %2;" : "=r"(r) : "f"(hi), "f"(lo));
    return r;
}
__device__ __forceinline__ u64 ffma2(u64 a, u64 b, u64 c) {
    u64 d; asm("fma.rn.f32x2 %0,%1,%2,%3;" : "=l"(d) : "l"(a), "l"(b), "l"(c)); return d;
}
__device__ __forceinline__ void up2(u64 v, float& lo, float& hi) {
    asm("mov.b64 {%0,%1},%2;" : "=f"(lo), "=f"(hi) : "l"(v));
}
__device__ __forceinline__ void cp16(u32 dst, const void* src) {
    asm volatile("cp.async.cg.shared.global [%0], [%1], 16;" :: "r"(dst), "l"(src));
}
// D += A(bf16) * B(bf16), fp32 accum, m16n8k16 row.col
__device__ __forceinline__ void mma_bf16(float d[4], const u32 a[4], const u32 b[2]) {
    asm volatile(
        "mma.sync.aligned.m16n8k16.row.col.f32.bf16.bf16.f32 "
        "{%0,%1,%2,%3},{%4,%5,%6,%7},{%8,%9},{%0,%1,%2,%3};"
        : "+f"(d[0]), "+f"(d[1]), "+f"(d[2]), "+f"(d[3])
        : "r"(a[0]), "r"(a[1]), "r"(a[2]), "r"(a[3]), "r"(b[0]), "r"(b[1]));
}

// ============================================================================
// Kernel W: convert qw + kvw (fp32) -> g_Wb (bf16).
// ============================================================================
__global__ void kw_conv(const float* __restrict__ qw, const float* __restrict__ kvw) {
    int i = blockIdx.x * blockDim.x + threadIdx.x;
    if (i < 384*128)
        g_Wb[i] = __float2bfloat16(i < 16384 ? qw[i] : kvw[i - 16384]);
}

// ============================================================================
// Kernel 0 v2: coalesced NCHW transpose + LayerNorm -> bf16 raw + LN'd.
//   144 CTAs x 256 threads; CTA = 64 consecutive pixels (same batch).
// ============================================================================
__global__ void __launch_bounds__(256)
k0_ln(const float* __restrict__ feat,
      const float* __restrict__ lnw, const float* __restrict__ lnb) {
    __shared__ float sA[64][129];
    __shared__ float sLw[128], sLb[128];
    __shared__ float sM[64], sR[64];

    int base = blockIdx.x * 64;          // global pixel base
    int b    = base / 2304;
    int p0   = base % 2304;
    int tid  = threadIdx.x;

    if (tid < 128) { sLw[tid] = lnw[tid]; sLb[tid] = lnb[tid]; }

    // coalesced load: lane = pixel within a 64-run of one channel
    const float* fb = feat + (size_t)b * CC * 2304 + p0;
#pragma unroll
    for (int i = 0; i < 32; i++) {
        int f = tid + i*256;
        int c = f >> 6, p = f & 63;
        sA[p][c] = fb[(size_t)c * 2304 + p];
    }
    __syncthreads();

    // LN stats: quad of consecutive lanes per pixel
    {
        int p = tid >> 2, tg = tid & 3;
        float s = 0.f, ss = 0.f;
#pragma unroll
        for (int k = 0; k < 32; k++) {
            float v = sA[p][tg*32 + k];
            s += v; ss += v*v;
        }
        s  += __shfl_xor_sync(0xffffffffu, s, 1);
        ss += __shfl_xor_sync(0xffffffffu, ss, 1);
        s  += __shfl_xor_sync(0xffffffffu, s, 2);
        ss += __shfl_xor_sync(0xffffffffu, ss, 2);
        float mean = s * (1.f/128.f);
        float var  = ss * (1.f/128.f) - mean*mean;
        if (tg == 0) { sM[p] = mean; sR[p] = rsqrtf(var + 1e-5f); }
    }
    __syncthreads();

    // coalesced bf16 stores: lane = u32 column within pixel row
    u32* dF = (u32*)g_Fb  + (size_t)base * 64;
    u32* dN = (u32*)g_FNb + (size_t)base * 64;
#pragma unroll
    for (int i = 0; i < 16; i++) {
        int f = tid + i*256;
        int p = f >> 6, col = f & 63;
        float v0 = sA[p][2*col], v1 = sA[p][2*col+1];
        float m = sM[p], r = sR[p];
        float n0 = (v0 - m)*r*sLw[2*col]   + sLb[2*col];
        float n1 = (v1 - m)*r*sLw[2*col+1] + sLb[2*col+1];
        dF[(size_t)p*64 + col] = packbf(v0, v1);
        dN[(size_t)p*64 + col] = packbf(n0, n1);
    }
}

// ============================================================================
// Kernel 1 v2: HMMA bf16 projection GEMMs.
//   grid (144, 3), 256 threads = 8 warps.  CTA = 64 pixels x 128 outs, K=128.
//   warp = (m-tile mw = w&3 [16 pixels], n-half nh = w>>2 [8 n-tiles]).
// ============================================================================
#define K1SMEM ((64*65 + 128*65)*4 + 512)    // sA + sW (u32) + bias

__global__ void __launch_bounds__(256)
k1_gemm(const float* __restrict__ qb, const float* __restrict__ kvb) {
    extern __shared__ u32 dsu[];
    u32* sAu = dsu;                    // [64][65]
    u32* sWu = dsu + 64*65;            // [128][65]
    float* sBias = (float*)(dsu + 64*65 + 128*65);   // [128]

    int sub   = blockIdx.y;
    int mBase = blockIdx.x * 64;
    int tid   = threadIdx.x;
    int lane  = tid & 31;
    int warp  = tid >> 5;
    int mw = warp & 3, nh = warp >> 2;
    int t4 = lane & 3, g4 = lane >> 2;

    const u32* A  = (const u32*)((sub == 0) ? g_FNb : g_Fb);
    const u32* Wm = (const u32*)g_Wb + (size_t)sub * 8192;
    const float* bias = (sub == 0) ? qb : (kvb + (sub-1)*128);

    if (tid < 128) sBias[tid] = bias[tid];
    // load A tile: 64 rows x 64 u32
#pragma unroll
    for (int i = 0; i < 16; i++) {
        int f = tid + i*256;
        int row = f >> 6, col = f & 63;
        sAu[row*65 + col] = A[(size_t)(mBase + row)*64 + col];
    }
    // load W sub: 128 rows x 64 u32
#pragma unroll
    for (int i = 0; i < 32; i++) {
        int f = tid + i*256;
        int row = f >> 6, col = f & 63;
        sWu[row*65 + col] = Wm[(size_t)row*64 + col];
    }
    __syncthreads();

    // A frags for this warp's m-tile
    u32 aA[8][4];
    {
        const u32* r0 = sAu + (mw*16 + g4)*65;
        const u32* r1 = sAu + (mw*16 + g4 + 8)*65;
#pragma unroll
        for (int s = 0; s < 8; s++) {
            aA[s][0] = r0[8*s + t4];
            aA[s][1] = r1[8*s + t4];
            aA[s][2] = r0[8*s + t4 + 4];
            aA[s][3] = r1[8*s + t4 + 4];
        }
    }

    float acc[8][4];
#pragma unroll
    for (int n = 0; n < 8; n++)
#pragma unroll
        for (int i = 0; i < 4; i++) acc[n][i] = 0.f;

#pragma unroll
    for (int n = 0; n < 8; n++) {
        const u32* wr = sWu + (nh*64 + n*8 + g4)*65;
#pragma unroll
        for (int s = 0; s < 8; s++) {
            u32 bW[2] = { wr[8*s + t4], wr[8*s + t4 + 4] };
            mma_bf16(acc[n], aA[s], bW);
        }
    }

    // epilogue: bias (+ scale for Q), pack bf16, store
    const float SC = 0.25f * 1.4426950408889634f;
    float sc = (sub == 0) ? SC : 1.f;
    int row0 = mBase + mw*16 + g4;
    u32* dst = (sub == 0) ? ((u32*)g_Qb) : ((u32*)g_KVh);
    int rstride = (sub == 0) ? 64 : 128;
    int cbase   = (sub == 0) ? 0  : (sub-1)*64;
#pragma unroll
    for (int n = 0; n < 8; n++) {
        int cn = nh*64 + n*8 + 2*t4;
        float b0 = sBias[cn], b1 = sBias[cn+1];
        u32 pk0 = packbf((acc[n][0] + b0)*sc, (acc[n][1] + b1)*sc);
        u32 pk1 = packbf((acc[n][2] + b0)*sc, (acc[n][3] + b1)*sc);
        int ucol = cbase + nh*32 + n*4 + t4;
        dst[(size_t)row0*rstride + ucol]     = pk0;
        dst[(size_t)(row0+8)*rstride + ucol] = pk1;
    }
}

// ============================================================================
// Kernel 2: pooled KV (bf16) + bias token.  Unchanged from R11.
// ============================================================================
__global__ void k2_pool(const float* __restrict__ kvb) {
    int t = blockIdx.x;
    int c = threadIdx.x;
    if (t < BB*576) {
        int b = t / 576, r = t % 576, my = r / 24, mx = r % 24;
        const __nv_bfloat16* base = g_KVh + ((size_t)((b*48 + my*2)*48 + mx*2))*256 + c;
        float v = __bfloat162float(base[0]) + __bfloat162float(base[256])
                + __bfloat162float(base[48*256]) + __bfloat162float(base[48*256 + 256]);
        g_KVmidh[(size_t)t*256 + c] = __float2bfloat16(v * 0.25f);
    } else if (t < BB*576 + BB*144) {
        int t2 = t - BB*576;
        int b = t2 / 144, r = t2 % 144, gy = r / 12, gx = r % 12;
        float v = 0.f;
#pragma unroll
        for (int i = 0; i < 4; i++)
#pragma unroll
            for (int j = 0; j < 4; j++)
                v += __bfloat162float(
                    g_KVh[((size_t)((b*48 + gy*4 + i)*48 + gx*4 + j))*256 + c]);
        g_KVgloh[(size_t)t2*256 + c] = __float2bfloat16(v * (1.f/16.f));
    } else {
        g_kvbh[c] = __float2bfloat16(kvb[c]);
    }
}

// ============================================================================
// Kernel 3 = R11 verbatim (best: 92.3us): HMMA flash attention with smem
// staging (depth-4 ring, 2 tiles/step, prefetch dist 2).
// ============================================================================
#define NSTEP 31
#define ROWB 264
#define SLOTB (32*ROWB)
#define SMEMB (4*SLOTB*2)           // 67584 B (== att+wsm epilogue need)

__global__ void __launch_bounds__(512, 1)
k3_attn(const float* __restrict__ feat, const float* __restrict__ ow,
        const float* __restrict__ ob,   float* __restrict__ out) {
    extern __shared__ float ds[];
    __nv_bfloat16* dsh = (__nv_bfloat16*)ds;

    int cta = blockIdx.x;
    int b = cta / 36, g = cta % 36;
    int gy = g / 6, gx = g % 6;
    int tid  = threadIdx.x;
    int lane = tid & 31;
    int warp = tid >> 5;
    int h = warp & 7, mh = warp >> 3;
    int t4 = lane & 3, g4 = lane >> 2;

    u32 aQ[2][4];
    {
        const u32* qp = (const u32*)g_Qb;
#pragma unroll
        for (int m = 0; m < 2; m++) {
            int wg = mh*2 + m;
            int wy = gy*2 + (wg>>1), wx = gx*2 + (wg&1);
            int qa = g4,     pya = wy*4 + (qa>>2), pxa = wx*4 + (qa&3);
            int qb2 = g4+8,  pyb = wy*4 + (qb2>>2), pxb = wx*4 + (qb2&3);
            size_t pa = (size_t)((b*48+pya)*48+pxa)*64 + h*8 + t4;
            size_t pb = (size_t)((b*48+pyb)*48+pxb)*64 + h*8 + t4;
            aQ[m][0] = qp[pa];     aQ[m][1] = qp[pb];
            aQ[m][2] = qp[pa+4];   aQ[m][3] = qp[pb+4];
        }
    }

    float o[2][2][4];
#pragma unroll
    for (int m = 0; m < 2; m++)
#pragma unroll
        for (int n = 0; n < 2; n++)
#pragma unroll
            for (int i = 0; i < 4; i++) o[m][n][i] = 0.f;
    float ls[2][2] = {{0.f,0.f},{0.f,0.f}};

    auto stage = [&](int s) {
#pragma unroll
        for (int c2 = 0; c2 < 2; c2++) {
            int flat = tid + c2*512;
            int tsel = flat >> 9;
            int row  = (flat >> 5) & 15;
            int ch   = flat & 31;
            int tt = 2*s + tsel;
            const char* src;
            if (tt < 16) {
                int wgl = tt >> 2, st = tt & 3;
                int id2 = st*16 + row;
                int y = (gy*2 + (wgl>>1))*4 + (id2>>3) - 2;
                int x = (gx*2 + (wgl&1))*4  + (id2&7)  - 2;
                src = ((unsigned)y < 48u && (unsigned)x < 48u)
                    ? (const char*)(g_KVh + ((size_t)((b*48+y)*48+x))*256)
                    : (const char*)g_kvbh;
            } else if (tt < 52) {
                src = (const char*)(g_KVmidh + ((size_t)(b*576 + (tt-16)*16 + row))*256);
            } else if (tt < 61) {
                src = (const char*)(g_KVgloh + ((size_t)(b*144 + (tt-52)*16 + row))*256);
            } else {
                src = (const char*)g_kvbh;
            }
            u32 dst = (u32)__cvta_generic_to_shared(
                dsh + (size_t)(s&3)*SLOTB + (tsel*16 + row)*ROWB) + ch*16;
            cp16(dst, src + ch*16);
        }
        asm volatile("cp.async.commit_group;");
    };

    auto compute = [&](const __nv_bfloat16* tile, int tt) {
        int m0 = 0, m1 = 2;
        if (tt < 16) {
            int wgl = tt >> 2;
            if ((wgl >> 1) != mh) return;
            m0 = wgl & 1; m1 = m0 + 1;
        }
        u32 bK[2][2];
#pragma unroll
        for (int n = 0; n < 2; n++) {
            const u32* kp = (const u32*)(tile + (n*8 + g4)*ROWB) + h*8 + t4;
            bK[n][0] = kp[0];
            bK[n][1] = kp[4];
        }
        u32 bV[2][2];
#pragma unroll
        for (int vd = 0; vd < 2; vd++) {
            int col = 128 + h*16 + vd*8 + g4;
            u32 l0 = (u32)*(const unsigned short*)(tile + (2*t4  )*ROWB + col);
            u32 h0 = (u32)*(const unsigned short*)(tile + (2*t4+1)*ROWB + col);
            u32 l1 = (u32)*(const unsigned short*)(tile + (2*t4+8)*ROWB + col);
            u32 h1 = (u32)*(const unsigned short*)(tile + (2*t4+9)*ROWB + col);
            bV[vd][0] = l0 | (h0 << 16);
            bV[vd][1] = l1 | (h1 << 16);
        }
        for (int m = m0; m < m1; m++) {
            float S[2][4];
#pragma unroll
            for (int n = 0; n < 2; n++) {
#pragma unroll
                for (int i = 0; i < 4; i++) S[n][i] = 0.f;
                mma_bf16(S[n], aQ[m], bK[n]);
#pragma unroll
                for (int i = 0; i < 4; i++) S[n][i] = ex2f(S[n][i]);
                ls[m][0] += S[n][0] + S[n][1];
                ls[m][1] += S[n][2] + S[n][3];
            }
            u32 aP[4];
            aP[0] = packbf(S[0][0], S[0][1]);
            aP[1] = packbf(S[0][2], S[0][3]);
            aP[2] = packbf(S[1][0], S[1][1]);
            aP[3] = packbf(S[1][2], S[1][3]);
#pragma unroll
            for (int vd = 0; vd < 2; vd++)
                mma_bf16(o[m][vd], aP, bV[vd]);
        }
    };

    stage(0);
    stage(1);
    for (int s = 0; s < NSTEP; s++) {
        if (s < NSTEP-1) {
            asm volatile("cp.async.wait_group 1;");
        } else {
            asm volatile("cp.async.wait_group 0;");
        }
        __syncthreads();
        if (s + 2 < NSTEP) stage(s+2);

        const __nv_bfloat16* buf = dsh + (size_t)(s&3)*SLOTB;
        int t0 = 2*s;
        compute(buf, t0);
        if (t0 + 1 < 61) compute(buf + 16*ROWB, t0 + 1);
    }
    __syncthreads();

#pragma unroll
    for (int m = 0; m < 2; m++)
#pragma unroll
        for (int r = 0; r < 2; r++) {
            float v = ls[m][r];
            v += __shfl_xor_sync(0xffffffffu, v, 1);
            v += __shfl_xor_sync(0xffffffffu, v, 2);
            ls[m][r] = v;
        }

    float* att = ds;
    float* wsm = ds + 64*132;
#pragma unroll
    for (int m = 0; m < 2; m++) {
        float inv0 = 1.f / ls[m][0];
        float inv1 = 1.f / ls[m][1];
        int r0 = mh*32 + m*16 + g4;
#pragma unroll
        for (int n = 0; n < 2; n++) {
            int col = h*16 + n*8 + 2*t4;
            *(float2*)&att[r0*132 + col]     = make_float2(o[m][n][0]*inv0, o[m][n][1]*inv0);
            *(float2*)&att[(r0+8)*132 + col] = make_float2(o[m][n][2]*inv1, o[m][n][3]*inv1);
        }
    }
    __syncthreads();

    int aqi = tid >> 3, og = tid & 7;
    float ov[16];
#pragma unroll 1
    for (int c2 = 0; c2 < 2; c2++) {
#pragma unroll
        for (int i = 0; i < 4; i++) {
            int f = tid + i*512;
            int row = f >> 5, quad = f & 31;
            *(float4*)&wsm[row*132 + quad*4] =
                *(const float4*)(ow + (size_t)(c2*64 + row)*128 + quad*4);
        }
        __syncthreads();

        u64 r[8];
#pragma unroll
        for (int u2 = 0; u2 < 8; u2++) r[u2] = 0ull;
#pragma unroll 4
        for (int k4 = 0; k4 < 32; k4++) {
            longlong2 av = *(const longlong2*)&att[aqi*132 + k4*4];
#pragma unroll
            for (int u2 = 0; u2 < 8; u2++) {
                longlong2 wv = *(const longlong2*)&wsm[(u2*8+og)*132 + k4*4];
                r[u2] = ffma2((u64)av.x, (u64)wv.x, r[u2]);
                r[u2] = ffma2((u64)av.y, (u64)wv.y, r[u2]);
            }
        }
#pragma unroll
        for (int u2 = 0; u2 < 8; u2++) {
            float a, bb;
            up2(r[u2], a, bb);
            ov[c2*8 + u2] = a + bb;
        }
        __syncthreads();
    }

    {
        int qi = aqi & 15, wq = aqi >> 4;
        int wy = gy*2 + (wq>>1), wx = gx*2 + (wq&1);
        int py = wy*4 + (qi>>2), px = wx*4 + (qi&3);
#pragma unroll
        for (int c2 = 0; c2 < 2; c2++) {
#pragma unroll
            for (int u2 = 0; u2 < 8; u2++) {
                int oc = c2*64 + u2*8 + og;
                size_t gi = (((size_t)b*128 + oc)*48 + py)*48 + px;
                out[gi] = ov[c2*8+u2] + ob[oc] + feat[gi];
            }
        }
    }
}

// ============================================================================
extern "C" void kernel_launch(void* const* d_in, const int* in_sizes, int n_in,
                              void* d_out, int out_size) {
    const float* feat = (const float*)d_in[0];
    const float* lnw  = (const float*)d_in[1];
    const float* lnb  = (const float*)d_in[2];
    const float* qw   = (const float*)d_in[3];
    const float* qb   = (const float*)d_in[4];
    const float* kvw  = (const float*)d_in[5];
    const float* kvb  = (const float*)d_in[6];
    const float* ow   = (const float*)d_in[7];
    const float* ob   = (const float*)d_in[8];
    float* out = (float*)d_out;

    cudaFuncSetAttribute(k1_gemm, cudaFuncAttributeMaxDynamicSharedMemorySize, K1SMEM);
    cudaFuncSetAttribute(k3_attn, cudaFuncAttributeMaxDynamicSharedMemorySize, SMEMB);

    kw_conv<<<192, 256>>>(qw, kvw);
    k0_ln<<<144, 256>>>(feat, lnw, lnb);
    k1_gemm<<<dim3(144, 3), 256, K1SMEM>>>(qb, kvb);
    k2_pool<<<2881, 256>>>(kvb);
    k3_attn<<<144, 512, SMEMB>>>(feat, ow, ob, out);
}

// round 14
// speedup vs baseline: 1.3639x; 1.0197x over previous
#include <cuda_runtime.h>
#include <cuda_bf16.h>
#include <cuda_fp16.h>
#include <cstdint>

#define BB 4
#define HH 48
#define WW 48
#define CC 128

typedef unsigned int u32;
typedef unsigned long long u64;

// ---------------- scratch (device globals; no allocation allowed) ----------
// NOTE: g_KVh / g_KVpool / g_kvbh hold MIXED types: bytes [0,256) of each
// 512-byte token row are bf16 K, bytes [256,512) are f16 V.
__device__ __nv_bfloat16 g_Fb [BB*HH*WW*CC];        // raw features, bf16 pixel-major
__device__ __nv_bfloat16 g_FNb[BB*HH*WW*CC];        // LN'd features, bf16
__device__ __nv_bfloat16 g_Wb [384*128];            // qw|kvw weights, bf16
__device__ __nv_bfloat16 g_Qb   [BB*HH*WW*CC];      // queries, bf16, pre-scaled
__device__ __nv_bfloat16 g_KVh  [BB*HH*WW*256];     // per-pixel K(bf16)|V(f16)
__device__ __nv_bfloat16 g_KVpool[BB*736*256];      // mid(576)+glo(144)+pad(16)
__device__ __nv_bfloat16 g_kvbh [256];              // bias token K(bf16)|V(f16)

__device__ __forceinline__ u32 packbf(float lo, float hi) {
    u32 r; asm("cvt.rn.satfinite.bf16x2.f32 %0, %1, %2;" : "=r"(r) : "f"(hi), "f"(lo));
    return r;
}
__device__ __forceinline__ u32 packf16(float lo, float hi) {
    u32 r; asm("cvt.rn.f16x2.f32 %0, %1, %2;" : "=r"(r) : "f"(hi), "f"(lo));
    return r;
}
__device__ __forceinline__ u32 ex2h2(u32 x) {
    u32 r; asm("ex2.approx.f16x2 %0, %1;" : "=r"(r) : "r"(x)); return r;
}
__device__ __forceinline__ u32 hadd2(u32 a, u32 b) {
    u32 r; asm("add.rn.f16x2 %0, %1, %2;" : "=r"(r) : "r"(a), "r"(b)); return r;
}
__device__ __forceinline__ void h2tof(u32 v, float& lo, float& hi) {
    asm("{.reg .b16 l,h; mov.b32 {l,h}, %2; cvt.f32.f16 %0, l; cvt.f32.f16 %1, h;}"
        : "=f"(lo), "=f"(hi) : "r"(v));
}
__device__ __forceinline__ u64 ffma2(u64 a, u64 b, u64 c) {
    u64 d; asm("fma.rn.f32x2 %0,%1,%2,%3;" : "=l"(d) : "l"(a), "l"(b), "l"(c)); return d;
}
__device__ __forceinline__ void up2(u64 v, float& lo, float& hi) {
    asm("mov.b64 {%0,%1},%2;" : "=f"(lo), "=f"(hi) : "l"(v));
}
__device__ __forceinline__ void cp16(u32 dst, const void* src) {
    asm volatile("cp.async.cg.shared.global [%0], [%1], 16;" :: "r"(dst), "l"(src));
}
// D += A(bf16) * B(bf16), fp32 accum
__device__ __forceinline__ void mma_bf16(float d[4], const u32 a[4], const u32 b[2]) {
    asm volatile(
        "mma.sync.aligned.m16n8k16.row.col.f32.bf16.bf16.f32 "
        "{%0,%1,%2,%3},{%4,%5,%6,%7},{%8,%9},{%0,%1,%2,%3};"
        : "+f"(d[0]), "+f"(d[1]), "+f"(d[2]), "+f"(d[3])
        : "r"(a[0]), "r"(a[1]), "r"(a[2]), "r"(a[3]), "r"(b[0]), "r"(b[1]));
}
// D += A(f16) * B(f16), fp32 accum
__device__ __forceinline__ void mma_f16(float d[4], const u32 a[4], const u32 b[2]) {
    asm volatile(
        "mma.sync.aligned.m16n8k16.row.col.f32.f16.f16.f32 "
        "{%0,%1,%2,%3},{%4,%5,%6,%7},{%8,%9},{%0,%1,%2,%3};"
        : "+f"(d[0]), "+f"(d[1]), "+f"(d[2]), "+f"(d[3])
        : "r"(a[0]), "r"(a[1]), "r"(a[2]), "r"(a[3]), "r"(b[0]), "r"(b[1]));
}

// ============================================================================
// Kernel W: convert qw + kvw (fp32) -> g_Wb (bf16).
// ============================================================================
__global__ void kw_conv(const float* __restrict__ qw, const float* __restrict__ kvw) {
    int i = blockIdx.x * blockDim.x + threadIdx.x;
    if (i < 384*128)
        g_Wb[i] = __float2bfloat16(i < 16384 ? qw[i] : kvw[i - 16384]);
}

// ============================================================================
// Kernel 0 v2: coalesced NCHW transpose + LayerNorm -> bf16 raw + LN'd.
// ============================================================================
__global__ void __launch_bounds__(256)
k0_ln(const float* __restrict__ feat,
      const float* __restrict__ lnw, const float* __restrict__ lnb) {
    __shared__ float sA[64][129];
    __shared__ float sLw[128], sLb[128];
    __shared__ float sM[64], sR[64];

    int base = blockIdx.x * 64;
    int b    = base / 2304;
    int p0   = base % 2304;
    int tid  = threadIdx.x;

    if (tid < 128) { sLw[tid] = lnw[tid]; sLb[tid] = lnb[tid]; }

    const float* fb = feat + (size_t)b * CC * 2304 + p0;
#pragma unroll
    for (int i = 0; i < 32; i++) {
        int f = tid + i*256;
        int c = f >> 6, p = f & 63;
        sA[p][c] = fb[(size_t)c * 2304 + p];
    }
    __syncthreads();

    {
        int p = tid >> 2, tg = tid & 3;
        float s = 0.f, ss = 0.f;
#pragma unroll
        for (int k = 0; k < 32; k++) {
            float v = sA[p][tg*32 + k];
            s += v; ss += v*v;
        }
        s  += __shfl_xor_sync(0xffffffffu, s, 1);
        ss += __shfl_xor_sync(0xffffffffu, ss, 1);
        s  += __shfl_xor_sync(0xffffffffu, s, 2);
        ss += __shfl_xor_sync(0xffffffffu, ss, 2);
        float mean = s * (1.f/128.f);
        float var  = ss * (1.f/128.f) - mean*mean;
        if (tg == 0) { sM[p] = mean; sR[p] = rsqrtf(var + 1e-5f); }
    }
    __syncthreads();

    u32* dF = (u32*)g_Fb  + (size_t)base * 64;
    u32* dN = (u32*)g_FNb + (size_t)base * 64;
#pragma unroll
    for (int i = 0; i < 16; i++) {
        int f = tid + i*256;
        int p = f >> 6, col = f & 63;
        float v0 = sA[p][2*col], v1 = sA[p][2*col+1];
        float m = sM[p], r = sR[p];
        float n0 = (v0 - m)*r*sLw[2*col]   + sLb[2*col];
        float n1 = (v1 - m)*r*sLw[2*col+1] + sLb[2*col+1];
        dF[(size_t)p*64 + col] = packbf(v0, v1);
        dN[(size_t)p*64 + col] = packbf(n0, n1);
    }
}

// ============================================================================
// Kernel 1 v2: HMMA bf16 projection GEMMs.  sub 2 (V) packs f16.
// ============================================================================
#define K1SMEM ((64*65 + 128*65)*4 + 512)

__global__ void __launch_bounds__(256)
k1_gemm(const float* __restrict__ qb, const float* __restrict__ kvb) {
    extern __shared__ u32 dsu[];
    u32* sAu = dsu;                    // [64][65]
    u32* sWu = dsu + 64*65;            // [128][65]
    float* sBias = (float*)(dsu + 64*65 + 128*65);

    int sub   = blockIdx.y;
    int mBase = blockIdx.x * 64;
    int tid   = threadIdx.x;
    int lane  = tid & 31;
    int warp  = tid >> 5;
    int mw = warp & 3, nh = warp >> 2;
    int t4 = lane & 3, g4 = lane >> 2;

    const u32* A  = (const u32*)((sub == 0) ? g_FNb : g_Fb);
    const u32* Wm = (const u32*)g_Wb + (size_t)sub * 8192;
    const float* bias = (sub == 0) ? qb : (kvb + (sub-1)*128);

    if (tid < 128) sBias[tid] = bias[tid];
#pragma unroll
    for (int i = 0; i < 16; i++) {
        int f = tid + i*256;
        int row = f >> 6, col = f & 63;
        sAu[row*65 + col] = A[(size_t)(mBase + row)*64 + col];
    }
#pragma unroll
    for (int i = 0; i < 32; i++) {
        int f = tid + i*256;
        int row = f >> 6, col = f & 63;
        sWu[row*65 + col] = Wm[(size_t)row*64 + col];
    }
    __syncthreads();

    u32 aA[8][4];
    {
        const u32* r0 = sAu + (mw*16 + g4)*65;
        const u32* r1 = sAu + (mw*16 + g4 + 8)*65;
#pragma unroll
        for (int s = 0; s < 8; s++) {
            aA[s][0] = r0[8*s + t4];
            aA[s][1] = r1[8*s + t4];
            aA[s][2] = r0[8*s + t4 + 4];
            aA[s][3] = r1[8*s + t4 + 4];
        }
    }

    float acc[8][4];
#pragma unroll
    for (int n = 0; n < 8; n++)
#pragma unroll
        for (int i = 0; i < 4; i++) acc[n][i] = 0.f;

#pragma unroll
    for (int n = 0; n < 8; n++) {
        const u32* wr = sWu + (nh*64 + n*8 + g4)*65;
#pragma unroll
        for (int s = 0; s < 8; s++) {
            u32 bW[2] = { wr[8*s + t4], wr[8*s + t4 + 4] };
            mma_bf16(acc[n], aA[s], bW);
        }
    }

    const float SC = 0.25f * 1.4426950408889634f;
    float sc = (sub == 0) ? SC : 1.f;
    int row0 = mBase + mw*16 + g4;
    u32* dst = (sub == 0) ? ((u32*)g_Qb) : ((u32*)g_KVh);
    int rstride = (sub == 0) ? 64 : 128;
    int cbase   = (sub == 0) ? 0  : (sub-1)*64;
#pragma unroll
    for (int n = 0; n < 8; n++) {
        int cn = nh*64 + n*8 + 2*t4;
        float b0 = sBias[cn], b1 = sBias[cn+1];
        float v00 = (acc[n][0] + b0)*sc, v01 = (acc[n][1] + b1)*sc;
        float v10 = (acc[n][2] + b0)*sc, v11 = (acc[n][3] + b1)*sc;
        u32 pk0, pk1;
        if (sub == 2) { pk0 = packf16(v00, v01); pk1 = packf16(v10, v11); }
        else          { pk0 = packbf (v00, v01); pk1 = packbf (v10, v11); }
        int ucol = cbase + nh*32 + n*4 + t4;
        dst[(size_t)row0*rstride + ucol]     = pk0;
        dst[(size_t)(row0+8)*rstride + ucol] = pk1;
    }
}

// ============================================================================
// Kernel 2: pooled KV into unified pool (K bf16 | V f16) + bias token.
// ============================================================================
__global__ void k2_pool(const float* __restrict__ kvb) {
    int t = blockIdx.x;
    int c = threadIdx.x;
    if (t < BB*576) {
        int b = t / 576, r = t % 576, my = r / 24, mx = r % 24;
        size_t p0 = (size_t)((b*48 + my*2)*48 + mx*2)*256 + c;
        size_t dp = ((size_t)(b*736 + r))*256 + c;
        if (c < 128) {
            const __nv_bfloat16* s = g_KVh + p0;
            float v = __bfloat162float(s[0]) + __bfloat162float(s[256])
                    + __bfloat162float(s[48*256]) + __bfloat162float(s[48*256+256]);
            g_KVpool[dp] = __float2bfloat16(v * 0.25f);
        } else {
            const __half* s = (const __half*)g_KVh + p0;
            float v = __half2float(s[0]) + __half2float(s[256])
                    + __half2float(s[48*256]) + __half2float(s[48*256+256]);
            ((__half*)g_KVpool)[dp] = __float2half(v * 0.25f);
        }
    } else if (t < BB*576 + BB*144) {
        int t2 = t - BB*576;
        int b = t2 / 144, r = t2 % 144, gy = r / 12, gx = r % 12;
        size_t dp = ((size_t)(b*736 + 576 + r))*256 + c;
        float v = 0.f;
        if (c < 128) {
#pragma unroll
            for (int i = 0; i < 4; i++)
#pragma unroll
                for (int j = 0; j < 4; j++)
                    v += __bfloat162float(
                        g_KVh[((size_t)((b*48 + gy*4 + i)*48 + gx*4 + j))*256 + c]);
            g_KVpool[dp] = __float2bfloat16(v * (1.f/16.f));
        } else {
#pragma unroll
            for (int i = 0; i < 4; i++)
#pragma unroll
                for (int j = 0; j < 4; j++)
                    v += __half2float(((const __half*)g_KVh)
                        [((size_t)((b*48 + gy*4 + i)*48 + gx*4 + j))*256 + c]);
            ((__half*)g_KVpool)[dp] = __float2half(v * (1.f/16.f));
        }
    } else {
        if (c < 128) g_kvbh[c] = __float2bfloat16(kvb[c]);
        else         ((__half*)g_kvbh)[c] = __float2half(kvb[c]);
    }
}

// ============================================================================
// Kernel 3 v12: HMMA flash attention (R11 skeleton) with
//   - unified pool staging (linear addresses for tiles >= 16, incl pad tile)
//   - f16 softmax: cvt.f16x2 + ex2.approx.f16x2 + add.f16x2 ls; PV mma f16.
// ============================================================================
#define NSTEP 31
#define ROWB 264
#define SLOTB (32*ROWB)
#define SMEMB (4*SLOTB*2)           // 67584 B

__global__ void __launch_bounds__(512, 1)
k3_attn(const float* __restrict__ feat, const float* __restrict__ ow,
        const float* __restrict__ ob,   float* __restrict__ out) {
    extern __shared__ float ds[];
    __nv_bfloat16* dsh = (__nv_bfloat16*)ds;

    int cta = blockIdx.x;
    int b = cta / 36, g = cta % 36;
    int gy = g / 6, gx = g % 6;
    int tid  = threadIdx.x;
    int lane = tid & 31;
    int warp = tid >> 5;
    int h = warp & 7, mh = warp >> 3;
    int t4 = lane & 3, g4 = lane >> 2;

    u32 aQ[2][4];
    {
        const u32* qp = (const u32*)g_Qb;
#pragma unroll
        for (int m = 0; m < 2; m++) {
            int wg = mh*2 + m;
            int wy = gy*2 + (wg>>1), wx = gx*2 + (wg&1);
            int qa = g4,     pya = wy*4 + (qa>>2), pxa = wx*4 + (qa&3);
            int qb2 = g4+8,  pyb = wy*4 + (qb2>>2), pxb = wx*4 + (qb2&3);
            size_t pa = (size_t)((b*48+pya)*48+pxa)*64 + h*8 + t4;
            size_t pb = (size_t)((b*48+pyb)*48+pxb)*64 + h*8 + t4;
            aQ[m][0] = qp[pa];     aQ[m][1] = qp[pb];
            aQ[m][2] = qp[pa+4];   aQ[m][3] = qp[pb+4];
        }
    }

    float o[2][2][4];
#pragma unroll
    for (int m = 0; m < 2; m++)
#pragma unroll
        for (int n = 0; n < 2; n++)
#pragma unroll
            for (int i = 0; i < 4; i++) o[m][n][i] = 0.f;
    u32 lsh[2][2] = {{0u,0u},{0u,0u}};      // f16x2 partial sums

    // staging: thread handles 2x 16B chunks per step
    auto stage = [&](int s) {
#pragma unroll
        for (int c2 = 0; c2 < 2; c2++) {
            int flat = tid + c2*512;
            int tsel = flat >> 9;
            int row  = (flat >> 5) & 15;
            int ch   = flat & 31;
            int tt = 2*s + tsel;
            const char* src;
            if (tt < 16) {
                int wgl = tt >> 2, st = tt & 3;
                int id2 = st*16 + row;
                int y = (gy*2 + (wgl>>1))*4 + (id2>>3) - 2;
                int x = (gx*2 + (wgl&1))*4  + (id2&7)  - 2;
                src = ((unsigned)y < 48u && (unsigned)x < 48u)
                    ? (const char*)(g_KVh + ((size_t)((b*48+y)*48+x))*256)
                    : (const char*)g_kvbh;
            } else {
                // unified pool: mid(0..575) glo(576..719) pad(720..735)
                src = (const char*)(g_KVpool
                      + ((size_t)(b*736) + (tt-16)*16 + row)*256);
            }
            u32 dst = (u32)__cvta_generic_to_shared(
                dsh + (size_t)(s&3)*SLOTB + (tsel*16 + row)*ROWB) + ch*16;
            cp16(dst, src + ch*16);
        }
        asm volatile("cp.async.commit_group;");
    };

    auto compute = [&](const __nv_bfloat16* tile, int tt) {
        int m0 = 0, m1 = 2;
        if (tt < 16) {
            int wgl = tt >> 2;
            if ((wgl >> 1) != mh) return;
            m0 = wgl & 1; m1 = m0 + 1;
        }
        u32 bK[2][2];
#pragma unroll
        for (int n = 0; n < 2; n++) {
            const u32* kp = (const u32*)(tile + (n*8 + g4)*ROWB) + h*8 + t4;
            bK[n][0] = kp[0];
            bK[n][1] = kp[4];
        }
        u32 bV[2][2];
#pragma unroll
        for (int vd = 0; vd < 2; vd++) {
            int col = 128 + h*16 + vd*8 + g4;
            u32 l0 = (u32)*(const unsigned short*)(tile + (2*t4  )*ROWB + col);
            u32 h0 = (u32)*(const unsigned short*)(tile + (2*t4+1)*ROWB + col);
            u32 l1 = (u32)*(const unsigned short*)(tile + (2*t4+8)*ROWB + col);
            u32 h1 = (u32)*(const unsigned short*)(tile + (2*t4+9)*ROWB + col);
            bV[vd][0] = l0 | (h0 << 16);
            bV[vd][1] = l1 | (h1 << 16);
        }
        for (int m = m0; m < m1; m++) {
            u32 aP[4];
#pragma unroll
            for (int n = 0; n < 2; n++) {
                float S[4];
#pragma unroll
                for (int i = 0; i < 4; i++) S[i] = 0.f;
                mma_bf16(S, aQ[m], bK[n]);
                u32 p01 = ex2h2(packf16(S[0], S[1]));   // row r0 token pair
                u32 p23 = ex2h2(packf16(S[2], S[3]));   // row r1 token pair
                lsh[m][0] = hadd2(lsh[m][0], p01);
                lsh[m][1] = hadd2(lsh[m][1], p23);
                aP[2*n]   = p01;
                aP[2*n+1] = p23;
            }
#pragma unroll
            for (int vd = 0; vd < 2; vd++)
                mma_f16(o[m][vd], aP, bV[vd]);
        }
    };

    stage(0);
    stage(1);
    for (int s = 0; s < NSTEP; s++) {
        if (s < NSTEP-1) {
            asm volatile("cp.async.wait_group 1;");
        } else {
            asm volatile("cp.async.wait_group 0;");
        }
        __syncthreads();
        if (s + 2 < NSTEP) stage(s+2);

        const __nv_bfloat16* buf = dsh + (size_t)(s&3)*SLOTB;
        int t0 = 2*s;
        compute(buf, t0);
        if (t0 + 1 < 61) compute(buf + 16*ROWB, t0 + 1);
    }
    __syncthreads();

    // ---- finalize ls: f16x2 -> f32, reduce across lane quads ----
    float ls[2][2];
#pragma unroll
    for (int m = 0; m < 2; m++)
#pragma unroll
        for (int r = 0; r < 2; r++) {
            float lo, hi;
            h2tof(lsh[m][r], lo, hi);
            float v = lo + hi;
            v += __shfl_xor_sync(0xffffffffu, v, 1);
            v += __shfl_xor_sync(0xffffffffu, v, 2);
            ls[m][r] = v;
        }

    float* att = ds;
    float* wsm = ds + 64*132;
#pragma unroll
    for (int m = 0; m < 2; m++) {
        float inv0 = 1.f / ls[m][0];
        float inv1 = 1.f / ls[m][1];
        int r0 = mh*32 + m*16 + g4;
#pragma unroll
        for (int n = 0; n < 2; n++) {
            int col = h*16 + n*8 + 2*t4;
            *(float2*)&att[r0*132 + col]     = make_float2(o[m][n][0]*inv0, o[m][n][1]*inv0);
            *(float2*)&att[(r0+8)*132 + col] = make_float2(o[m][n][2]*inv1, o[m][n][3]*inv1);
        }
    }
    __syncthreads();

    int aqi = tid >> 3, og = tid & 7;
    float ov[16];
#pragma unroll 1
    for (int c2 = 0; c2 < 2; c2++) {
#pragma unroll
        for (int i = 0; i < 4; i++) {
            int f = tid + i*512;
            int row = f >> 5, quad = f & 31;
            *(float4*)&wsm[row*132 + quad*4] =
                *(const float4*)(ow + (size_t)(c2*64 + row)*128 + quad*4);
        }
        __syncthreads();

        u64 r[8];
#pragma unroll
        for (int u2 = 0; u2 < 8; u2++) r[u2] = 0ull;
#pragma unroll 4
        for (int k4 = 0; k4 < 32; k4++) {
            longlong2 av = *(const longlong2*)&att[aqi*132 + k4*4];
#pragma unroll
            for (int u2 = 0; u2 < 8; u2++) {
                longlong2 wv = *(const longlong2*)&wsm[(u2*8+og)*132 + k4*4];
                r[u2] = ffma2((u64)av.x, (u64)wv.x, r[u2]);
                r[u2] = ffma2((u64)av.y, (u64)wv.y, r[u2]);
            }
        }
#pragma unroll
        for (int u2 = 0; u2 < 8; u2++) {
            float a, bb;
            up2(r[u2], a, bb);
            ov[c2*8 + u2] = a + bb;
        }
        __syncthreads();
    }

    {
        int qi = aqi & 15, wq = aqi >> 4;
        int wy = gy*2 + (wq>>1), wx = gx*2 + (wq&1);
        int py = wy*4 + (qi>>2), px = wx*4 + (qi&3);
#pragma unroll
        for (int c2 = 0; c2 < 2; c2++) {
#pragma unroll
            for (int u2 = 0; u2 < 8; u2++) {
                int oc = c2*64 + u2*8 + og;
                size_t gi = (((size_t)b*128 + oc)*48 + py)*48 + px;
                out[gi] = ov[c2*8+u2] + ob[oc] + feat[gi];
            }
        }
    }
}

// ============================================================================
extern "C" void kernel_launch(void* const* d_in, const int* in_sizes, int n_in,
                              void* d_out, int out_size) {
    const float* feat = (const float*)d_in[0];
    const float* lnw  = (const float*)d_in[1];
    const float* lnb  = (const float*)d_in[2];
    const float* qw   = (const float*)d_in[3];
    const float* qb   = (const float*)d_in[4];
    const float* kvw  = (const float*)d_in[5];
    const float* kvb  = (const float*)d_in[6];
    const float* ow   = (const float*)d_in[7];
    const float* ob   = (const float*)d_in[8];
    float* out = (float*)d_out;

    cudaFuncSetAttribute(k1_gemm, cudaFuncAttributeMaxDynamicSharedMemorySize, K1SMEM);
    cudaFuncSetAttribute(k3_attn, cudaFuncAttributeMaxDynamicSharedMemorySize, SMEMB);

    kw_conv<<<192, 256>>>(qw, kvw);
    k0_ln<<<144, 256>>>(feat, lnw, lnb);
    k1_gemm<<<dim3(144, 3), 256, K1SMEM>>>(qb, kvb);
    k2_pool<<<2881, 256>>>(kvb);
    k3_attn<<<144, 512, SMEMB>>>(feat, ow, ob, out);
}